// round 15
// baseline (speedup 1.0000x reference)
#include <cuda_runtime.h>
#include <cstdint>
#include <cstddef>

#define TSTEPS 32
#define INF    27
#define XROW_W 17   // u32 words per bf16 x row (k 0..31 used by mma, pads 0)
#define HROW_W 12   // u32 words per bf16 h row (k 0..15 used, words 5..7 = 0)
#define GPAD   36   // s_g row stride in floats (2-phase-optimal STS/LDS.64)

__device__ __forceinline__ void cp8(uint32_t saddr, const void* gptr){
  asm volatile("cp.async.ca.shared.global [%0], [%1], 8;" :: "r"(saddr), "l"(gptr));
}
__device__ __forceinline__ float tanh_fast(float x){
  float r; asm("tanh.approx.f32 %0, %1;" : "=f"(r) : "f"(x)); return r;
}
__device__ __forceinline__ float sig_from_half(float a){   // acc holds x/2
  return fmaf(0.5f, tanh_fast(a), 0.5f);
}
__device__ __forceinline__ uint32_t bf16pair(float lo_val, float hi_val){
  uint32_t r; asm("cvt.rn.bf16x2.f32 %0, %1, %2;" : "=r"(r) : "f"(hi_val), "f"(lo_val));
  return r;
}
#define MMA_BF16(C, A, B0, B1) \
  asm volatile("mma.sync.aligned.m16n8k16.row.col.f32.bf16.bf16.f32 " \
    "{%0,%1,%2,%3}, {%4,%5,%6,%7}, {%8,%9}, {%0,%1,%2,%3};" \
    : "+f"((C)[0]), "+f"((C)[1]), "+f"((C)[2]), "+f"((C)[3]) \
    : "r"((A)[0]), "r"((A)[1]), "r"((A)[2]), "r"((A)[3]), \
      "r"(B0), "r"(B1))

// Single-warp blocks, 32 elems each. Per step BOTH matvecs run on tensor
// cores: gates = W_ih@x + W_hh@h + b, accumulated in one set of C fragments
// (bf16 hi/lo split, 3 passes each). Recurrence is only activations + cell
// update. h is re-packed to a bf16 smem B-region each step.
__global__ void __launch_bounds__(32, 13) lstm_mma_kernel(
    const float* __restrict__ word,
    const float* __restrict__ W_ih, const float* __restrict__ W_hh,
    const float* __restrict__ b_ih, const float* __restrict__ b_hh,
    const float* __restrict__ W_fc, const float* __restrict__ b_fc,
    const float* __restrict__ W_out, const float* __restrict__ b_out,
    float* __restrict__ out, int Bn)
{
  __shared__ __align__(16) float   s_x[32*INF];       // fp32 x staging
  __shared__ __align__(8) uint32_t s_xhi[32*XROW_W];  // x bf16 hi
  __shared__ __align__(8) uint32_t s_xlo[32*XROW_W];  // x bf16 lo
  __shared__ __align__(8) uint32_t s_hhi[32*HROW_W];  // h bf16 hi (B-frag layout)
  __shared__ __align__(8) uint32_t s_hlo[32*HROW_W];  // h bf16 lo
  __shared__ __align__(8) float    s_g[40*GPAD];      // gate preactivations

  const int lane = threadIdx.x;
  const int gr = lane >> 2, cl = lane & 3;     // mma fragment coords
  const int half = lane & 1, p = lane >> 1;    // recurrence pairing
  const int e0 = 2*p;
  const int blockElem = blockIdx.x * 32;
  const uint32_t sx0 = (uint32_t)__cvta_generic_to_shared(&s_x[0]);

  // stage t=0 x early (432 float2 over 32 lanes)
  {
    const float2* src = (const float2*)(word + ((size_t)blockElem) * INF);
    #pragma unroll
    for (int m = 0; m < 14; m++){
      int i2 = m*32 + lane;
      if (i2 < 432) cp8(sx0 + (uint32_t)(i2*8), src + i2);
    }
    asm volatile("cp.async.commit_group;");
  }

  // zero h region (h_0 = 0; words 5..7 stay 0 forever as k-pad) and x pads
  #pragma unroll
  for (int m = 0; m < HROW_W; m++){
    s_hhi[lane*HROW_W + m] = 0u;
    s_hlo[lane*HROW_W + m] = 0u;
  }
  s_xhi[lane*XROW_W + 14] = 0u; s_xhi[lane*XROW_W + 15] = 0u; s_xhi[lane*XROW_W + 16] = 0u;
  s_xlo[lane*XROW_W + 14] = 0u; s_xlo[lane*XROW_W + 15] = 0u; s_xlo[lane*XROW_W + 16] = 0u;

  // ---- W_ih fragments (hi/lo bf16 split), i/f/o rows pre-halved (verified) ----
  uint32_t Ahi[3][2][4], Alo[3][2][4];
  float cb0[3], cb1[3];
  #pragma unroll
  for (int mi = 0; mi < 3; mi++){
    int r0 = 16*mi + gr, r1 = r0 + 8;
    float s0 = (r0 < 20 || r0 >= 30) ? 0.5f : 1.0f;
    float s1 = (r1 < 20 || r1 >= 30) ? 0.5f : 1.0f;
    cb0[mi] = (r0 < 40) ? s0 * (b_ih[r0] + b_hh[r0]) : 0.f;
    cb1[mi] = (r1 < 40) ? s1 * (b_ih[r1] + b_hh[r1]) : 0.f;
    #pragma unroll
    for (int ki = 0; ki < 2; ki++){
      #pragma unroll
      for (int q = 0; q < 4; q++){
        int r = (q & 1) ? r1 : r0;
        int c = 16*ki + 2*cl + ((q >> 1) ? 8 : 0);
        float sc = (r < 20 || r >= 30) ? 0.5f : 1.0f;
        float w0 = (r < 40 && c     < 27) ? sc * W_ih[r*27 + c    ] : 0.f;
        float w1 = (r < 40 && c + 1 < 27) ? sc * W_ih[r*27 + c + 1] : 0.f;
        uint32_t h2 = bf16pair(w0, w1);
        float h0 = __uint_as_float(h2 << 16);
        float h1 = __uint_as_float(h2 & 0xffff0000u);
        Ahi[mi][ki][q] = h2;
        Alo[mi][ki][q] = bf16pair(w0 - h0, w1 - h1);
      }
    }
  }
  // ---- W_hh fragments (hi/lo bf16 split), same row scaling; K=10 pad 16 ----
  uint32_t Hhi[3][4], Hlo[3][4];
  #pragma unroll
  for (int mi = 0; mi < 3; mi++){
    int r0 = 16*mi + gr, r1 = r0 + 8;
    #pragma unroll
    for (int q = 0; q < 4; q++){
      int r = (q & 1) ? r1 : r0;
      int c = 2*cl + ((q >> 1) ? 8 : 0);
      float sc = (r < 20 || r >= 30) ? 0.5f : 1.0f;
      float w0 = (r < 40 && c     < 10) ? sc * W_hh[r*10 + c    ] : 0.f;
      float w1 = (r < 40 && c + 1 < 10) ? sc * W_hh[r*10 + c + 1] : 0.f;
      uint32_t h2 = bf16pair(w0, w1);
      float h0 = __uint_as_float(h2 << 16);
      float h1 = __uint_as_float(h2 & 0xffff0000u);
      Hhi[mi][q] = h2;
      Hlo[mi][q] = bf16pair(w0 - h0, w1 - h1);
    }
  }
  __syncwarp();

  float cA[5], cB[5], hA[10], hB[10];
  #pragma unroll
  for (int k = 0; k < 5;  k++){ cA[k]=0.f; cB[k]=0.f; }
  #pragma unroll
  for (int k = 0; k < 10; k++){ hA[k]=0.f; hB[k]=0.f; }

  #pragma unroll 1
  for (int t = 0; t < TSTEPS; t++){
    asm volatile("cp.async.wait_group 0;");
    __syncwarp();   // x[t] staged; previous step's h stores visible

    // ---- convert own elem row fp32 -> bf16 hi/lo ----
    {
      const float* xr = &s_x[lane * INF];
      const uint32_t hb = (uint32_t)(lane * XROW_W);
      #pragma unroll
      for (int m = 0; m < 14; m++){
        float x0 = xr[2*m];
        float x1 = (2*m + 1 < INF) ? xr[2*m + 1] : 0.f;
        uint32_t h2 = bf16pair(x0, x1);
        float h0 = __uint_as_float(h2 << 16);
        float h1 = __uint_as_float(h2 & 0xffff0000u);
        s_xhi[hb + m] = h2;
        s_xlo[hb + m] = bf16pair(x0 - h0, x1 - h1);
      }
    }
    __syncwarp();   // conversions visible; s_x free for restage

    // ---- stage x_{t+1} ----
    if (t + 1 < TSTEPS){
      const float2* src = (const float2*)(word + ((size_t)(t+1)*Bn + blockElem) * INF);
      #pragma unroll
      for (int m = 0; m < 14; m++){
        int i2 = m*32 + lane;
        if (i2 < 432) cp8(sx0 + (uint32_t)(i2*8), src + i2);
      }
      asm volatile("cp.async.commit_group;");
    }

    // ---- gates = W_ih@x + W_hh@h + bias, all in C fragments ----
    float C[3][4][4];
    #pragma unroll
    for (int mi = 0; mi < 3; mi++)
      #pragma unroll
      for (int ni = 0; ni < 4; ni++){
        C[mi][ni][0] = cb0[mi]; C[mi][ni][1] = cb0[mi];
        C[mi][ni][2] = cb1[mi]; C[mi][ni][3] = cb1[mi];
      }
    // x passes (3-pass hi/lo split)
    #pragma unroll
    for (int ki = 0; ki < 2; ki++){
      #pragma unroll
      for (int ni = 0; ni < 4; ni++){
        int n = 8*ni + gr;
        uint32_t bh0 = s_xhi[n*XROW_W + 8*ki + cl];
        uint32_t bh1 = s_xhi[n*XROW_W + 8*ki + cl + 4];
        #pragma unroll
        for (int mi = 0; mi < 3; mi++){
          MMA_BF16(C[mi][ni], Ahi[mi][ki], bh0, bh1);   // Whi * xhi
          MMA_BF16(C[mi][ni], Alo[mi][ki], bh0, bh1);   // Wlo * xhi
        }
        uint32_t bl0 = s_xlo[n*XROW_W + 8*ki + cl];
        uint32_t bl1 = s_xlo[n*XROW_W + 8*ki + cl + 4];
        #pragma unroll
        for (int mi = 0; mi < 3; mi++)
          MMA_BF16(C[mi][ni], Ahi[mi][ki], bl0, bl1);   // Whi * xlo
      }
    }
    // h passes (K=16, single ki; 3-pass hi/lo split)
    #pragma unroll
    for (int ni = 0; ni < 4; ni++){
      int n = 8*ni + gr;
      uint32_t bh0 = s_hhi[n*HROW_W + cl];
      uint32_t bh1 = s_hhi[n*HROW_W + cl + 4];
      #pragma unroll
      for (int mi = 0; mi < 3; mi++){
        MMA_BF16(C[mi][ni], Hhi[mi], bh0, bh1);         // Uhi * hhi
        MMA_BF16(C[mi][ni], Hlo[mi], bh0, bh1);         // Ulo * hhi
      }
      uint32_t bl0 = s_hlo[n*HROW_W + cl];
      uint32_t bl1 = s_hlo[n*HROW_W + cl + 4];
      #pragma unroll
      for (int mi = 0; mi < 3; mi++)
        MMA_BF16(C[mi][ni], Hhi[mi], bl0, bl1);         // Uhi * hlo
    }
    // ---- store gates: C frag -> s_g[row][elem] ----
    #pragma unroll
    for (int mi = 0; mi < 3; mi++)
      #pragma unroll
      for (int ni = 0; ni < 4; ni++){
        int row0 = 16*mi + gr;
        int col  = 8*ni + 2*cl;
        *(float2*)&s_g[row0*GPAD + col] = make_float2(C[mi][ni][0], C[mi][ni][1]);
        if (mi < 2)
          *(float2*)&s_g[(row0+8)*GPAD + col] = make_float2(C[mi][ni][2], C[mi][ni][3]);
      }
    __syncwarp();

    // ---- recurrence: activations + cell update only (no matvec) ----
    float hnA[5], hnB[5];
    #pragma unroll
    for (int kk = 0; kk < 5; kk++){
      const int ri = 2*kk + half;
      float2 vi = *(const float2*)&s_g[(ri     )*GPAD + e0];
      float2 vf = *(const float2*)&s_g[(ri + 10)*GPAD + e0];
      float2 vg = *(const float2*)&s_g[(ri + 20)*GPAD + e0];
      float2 vo = *(const float2*)&s_g[(ri + 30)*GPAD + e0];
      float i0 = sig_from_half(vi.x), i1 = sig_from_half(vi.y);
      float f0 = sig_from_half(vf.x), f1 = sig_from_half(vf.y);
      float g0 = tanh_fast(vg.x),     g1 = tanh_fast(vg.y);
      float o0 = sig_from_half(vo.x), o1 = sig_from_half(vo.y);
      float cn0 = fmaf(f0, cA[kk], i0*g0);
      float cn1 = fmaf(f1, cB[kk], i1*g1);
      float hv0 = o0 * tanh_fast(cn0);
      float hv1 = o1 * tanh_fast(cn1);
      cA[kk]  = fmaxf(cn0, 0.f);       // ReLU on carried cell state
      cB[kk]  = fmaxf(cn1, 0.f);
      hnA[kk] = fmaxf(hv0, 0.f);       // ReLU on carried hidden
      hnB[kk] = fmaxf(hv1, 0.f);
    }
    // exchange halves -> full h for both elements (verified R14 block)
    #pragma unroll
    for (int kk = 0; kk < 5; kk++){
      float oA = __shfl_xor_sync(0xFFFFFFFFu, hnA[kk], 1);
      float oB = __shfl_xor_sync(0xFFFFFFFFu, hnB[kk], 1);
      hA[2*kk + half]     = hnA[kk];  hA[2*kk + 1 - half] = oA;
      hB[2*kk + half]     = hnB[kk];  hB[2*kk + 1 - half] = oB;
    }
    // ---- pack h (own element = lane) into bf16 hi/lo B-frag rows ----
    {
      const float* hw = half ? hB : hA;      // lane's own element's h
      const uint32_t hb = (uint32_t)(lane * HROW_W);
      #pragma unroll
      for (int m = 0; m < 5; m++){
        float a = hw[2*m], b = hw[2*m + 1];
        uint32_t h2 = bf16pair(a, b);
        float a_hi = __uint_as_float(h2 << 16);
        float b_hi = __uint_as_float(h2 & 0xffff0000u);
        s_hhi[hb + m] = h2;
        s_hlo[hb + m] = bf16pair(a - a_hi, b - b_hi);
      }
    }
    // visibility for next step's MMA reads: covered by next-iteration syncwarps
  }

  // ---- head: FC(10->5) -> ReLU -> Linear(5->1) -> sigmoid (params via LDG) ----
  if (half == 0){
    float z0 = b_out[0], z1 = z0;
    #pragma unroll
    for (int u = 0; u < 5; u++){
      float y0 = b_fc[u], y1 = y0;
      #pragma unroll
      for (int k = 0; k < 10; k++){
        float w = W_fc[u*10 + k];
        y0 = fmaf(w, hA[k], y0);
        y1 = fmaf(w, hB[k], y1);
      }
      float wo = W_out[u];
      z0 = fmaf(wo, fmaxf(y0, 0.f), z0);
      z1 = fmaf(wo, fmaxf(y1, 0.f), z1);
    }
    const int b0 = blockElem + e0;
    if (b0 + 1 < Bn){
      float2 v;
      v.x = fmaf(0.5f, tanh_fast(0.5f * z0), 0.5f);
      v.y = fmaf(0.5f, tanh_fast(0.5f * z1), 0.5f);
      *(float2*)(out + b0) = v;
    } else if (b0 < Bn){
      out[b0] = fmaf(0.5f, tanh_fast(0.5f * z0), 0.5f);
    }
  }
}

extern "C" void kernel_launch(void* const* d_in, const int* in_sizes, int n_in,
                              void* d_out, int out_size) {
  const float* word  = (const float*)d_in[0];
  const float* W_ih  = (const float*)d_in[1];
  const float* W_hh  = (const float*)d_in[2];
  const float* b_ih  = (const float*)d_in[3];
  const float* b_hh  = (const float*)d_in[4];
  const float* W_fc  = (const float*)d_in[5];
  const float* b_fc  = (const float*)d_in[6];
  const float* W_out = (const float*)d_in[7];
  const float* b_out = (const float*)d_in[8];
  float* out = (float*)d_out;

  const int Bn = in_sizes[0] / (TSTEPS * INF);   // 65536
  const int blocks = (Bn + 31) / 32;             // 2048 single-warp blocks

  lstm_mma_kernel<<<blocks, 32>>>(word, W_ih, W_hh, b_ih, b_hh,
                                  W_fc, b_fc, W_out, b_out, out, Bn);
}

// round 16
// speedup vs baseline: 1.0971x; 1.0971x over previous
#include <cuda_runtime.h>
#include <cstdint>
#include <cstddef>

#define TSTEPS 32
#define INF    27
#define XROW_W 17   // u32 words per bf16 x row (k 0..31 used by mma, pads 0)
#define HROW_W 9    // u32 words per bf16 h row (k 0..15; words 5..8 = 0 pad)
#define GPAD   34   // s_g row stride in floats

__device__ __forceinline__ void cp8(uint32_t saddr, const void* gptr){
  asm volatile("cp.async.ca.shared.global [%0], [%1], 8;" :: "r"(saddr), "l"(gptr));
}
__device__ __forceinline__ float tanh_fast(float x){
  float r; asm("tanh.approx.f32 %0, %1;" : "=f"(r) : "f"(x)); return r;
}
__device__ __forceinline__ float sig_from_half(float a){   // acc holds x/2
  return fmaf(0.5f, tanh_fast(a), 0.5f);
}
__device__ __forceinline__ uint32_t bf16pair(float lo_val, float hi_val){
  uint32_t r; asm("cvt.rn.bf16x2.f32 %0, %1, %2;" : "=r"(r) : "f"(hi_val), "f"(lo_val));
  return r;
}
#define MMA_BF16(C, A, B0, B1) \
  asm volatile("mma.sync.aligned.m16n8k16.row.col.f32.bf16.bf16.f32 " \
    "{%0,%1,%2,%3}, {%4,%5,%6,%7}, {%8,%9}, {%0,%1,%2,%3};" \
    : "+f"((C)[0]), "+f"((C)[1]), "+f"((C)[2]), "+f"((C)[3]) \
    : "r"((A)[0]), "r"((A)[1]), "r"((A)[2]), "r"((A)[3]), \
      "r"(B0), "r"(B1))

// re-init C with bias
#define C_INIT() do { \
  _Pragma("unroll") \
  for (int mi = 0; mi < 3; mi++) \
    _Pragma("unroll") \
    for (int ni = 0; ni < 4; ni++){ \
      C[mi][ni][0] = cb0[mi]; C[mi][ni][1] = cb0[mi]; \
      C[mi][ni][2] = cb1[mi]; C[mi][ni][3] = cb1[mi]; \
    } \
} while(0)

// C += W_ih @ x (3-pass bf16 hi/lo split) from s_xhi/s_xlo
#define X_PASSES() do { \
  _Pragma("unroll") \
  for (int ki = 0; ki < 2; ki++){ \
    _Pragma("unroll") \
    for (int ni = 0; ni < 4; ni++){ \
      int n = 8*ni + gr; \
      uint32_t bh0 = s_xhi[n*XROW_W + 8*ki + cl]; \
      uint32_t bh1 = s_xhi[n*XROW_W + 8*ki + cl + 4]; \
      _Pragma("unroll") \
      for (int mi = 0; mi < 3; mi++){ \
        MMA_BF16(C[mi][ni], Ahi[mi][ki], bh0, bh1); \
        MMA_BF16(C[mi][ni], Alo[mi][ki], bh0, bh1); \
      } \
      uint32_t bl0 = s_xlo[n*XROW_W + 8*ki + cl]; \
      uint32_t bl1 = s_xlo[n*XROW_W + 8*ki + cl + 4]; \
      _Pragma("unroll") \
      for (int mi = 0; mi < 3; mi++) \
        MMA_BF16(C[mi][ni], Ahi[mi][ki], bl0, bl1); \
    } \
  } \
} while(0)

// stage x_(tn) into s_x via cp.async (cooperative, 432 float2)
#define STAGE_X(tn) do { \
  const float2* _src = (const float2*)(word + ((size_t)(tn)*Bn + blockElem) * INF); \
  _Pragma("unroll") \
  for (int m = 0; m < 14; m++){ \
    int i2 = m*32 + lane; \
    if (i2 < 432) cp8(sx0 + (uint32_t)(i2*8), _src + i2); \
  } \
  asm volatile("cp.async.commit_group;"); \
} while(0)

// convert own element's fp32 row -> bf16 hi/lo rows
#define CONVERT_X() do { \
  const float* _xr = &s_x[lane * INF]; \
  const uint32_t _hb = (uint32_t)(lane * XROW_W); \
  _Pragma("unroll") \
  for (int m = 0; m < 14; m++){ \
    float _x0 = _xr[2*m]; \
    float _x1 = (2*m + 1 < INF) ? _xr[2*m + 1] : 0.f; \
    uint32_t _h2 = bf16pair(_x0, _x1); \
    float _h0 = __uint_as_float(_h2 << 16); \
    float _h1 = __uint_as_float(_h2 & 0xffff0000u); \
    s_xhi[_hb + m] = _h2; \
    s_xlo[_hb + m] = bf16pair(_x0 - _h0, _x1 - _h1); \
  } \
} while(0)

// Single-warp blocks, 32 elems, 14 blocks/SM (single wave). Pipelined:
// C carries bias + W_ih@x one step AHEAD; per step the serial chain is only
// h-MMA -> gate store -> activations -> pack h. The next step's x-GEMM and
// conversion overlap the recurrence (independent instruction streams).
__global__ void __launch_bounds__(32, 14) lstm_mma_kernel(
    const float* __restrict__ word,
    const float* __restrict__ W_ih, const float* __restrict__ W_hh,
    const float* __restrict__ b_ih, const float* __restrict__ b_hh,
    const float* __restrict__ W_fc, const float* __restrict__ b_fc,
    const float* __restrict__ W_out, const float* __restrict__ b_out,
    float* __restrict__ out, int Bn)
{
  __shared__ __align__(16) float   s_x[32*INF];       // fp32 x staging
  __shared__ __align__(8) uint32_t s_xhi[32*XROW_W];  // x bf16 hi
  __shared__ __align__(8) uint32_t s_xlo[32*XROW_W];  // x bf16 lo
  __shared__ __align__(8) uint32_t s_hhi[32*HROW_W];  // h bf16 hi
  __shared__ __align__(8) uint32_t s_hlo[32*HROW_W];  // h bf16 lo
  __shared__ __align__(8) float    s_g[40*GPAD];      // gate preactivations

  const int lane = threadIdx.x;
  const int gr = lane >> 2, cl = lane & 3;     // mma fragment coords
  const int half = lane & 1, p = lane >> 1;    // recurrence pairing
  const int e0 = 2*p;
  const int blockElem = blockIdx.x * 32;
  const uint32_t sx0 = (uint32_t)__cvta_generic_to_shared(&s_x[0]);

  STAGE_X(0);

  // zero h region (h_0 = 0; words 5..8 remain 0 as k-pad) and x row tails
  #pragma unroll
  for (int m = 0; m < HROW_W; m++){
    s_hhi[lane*HROW_W + m] = 0u;
    s_hlo[lane*HROW_W + m] = 0u;
  }
  s_xhi[lane*XROW_W + 14] = 0u; s_xhi[lane*XROW_W + 15] = 0u; s_xhi[lane*XROW_W + 16] = 0u;
  s_xlo[lane*XROW_W + 14] = 0u; s_xlo[lane*XROW_W + 15] = 0u; s_xlo[lane*XROW_W + 16] = 0u;

  // ---- W_ih fragments (hi/lo bf16 split), i/f/o rows pre-halved (verified) ----
  uint32_t Ahi[3][2][4], Alo[3][2][4];
  float cb0[3], cb1[3];
  #pragma unroll
  for (int mi = 0; mi < 3; mi++){
    int r0 = 16*mi + gr, r1 = r0 + 8;
    float s0 = (r0 < 20 || r0 >= 30) ? 0.5f : 1.0f;
    float s1 = (r1 < 20 || r1 >= 30) ? 0.5f : 1.0f;
    cb0[mi] = (r0 < 40) ? s0 * (b_ih[r0] + b_hh[r0]) : 0.f;
    cb1[mi] = (r1 < 40) ? s1 * (b_ih[r1] + b_hh[r1]) : 0.f;
    #pragma unroll
    for (int ki = 0; ki < 2; ki++){
      #pragma unroll
      for (int q = 0; q < 4; q++){
        int r = (q & 1) ? r1 : r0;
        int c = 16*ki + 2*cl + ((q >> 1) ? 8 : 0);
        float sc = (r < 20 || r >= 30) ? 0.5f : 1.0f;
        float w0 = (r < 40 && c     < 27) ? sc * W_ih[r*27 + c    ] : 0.f;
        float w1 = (r < 40 && c + 1 < 27) ? sc * W_ih[r*27 + c + 1] : 0.f;
        uint32_t h2 = bf16pair(w0, w1);
        float h0 = __uint_as_float(h2 << 16);
        float h1 = __uint_as_float(h2 & 0xffff0000u);
        Ahi[mi][ki][q] = h2;
        Alo[mi][ki][q] = bf16pair(w0 - h0, w1 - h1);
      }
    }
  }
  // ---- W_hh fragments (hi/lo bf16 split), K=10 padded to 16 (verified) ----
  uint32_t Hhi[3][4], Hlo[3][4];
  #pragma unroll
  for (int mi = 0; mi < 3; mi++){
    int r0 = 16*mi + gr, r1 = r0 + 8;
    #pragma unroll
    for (int q = 0; q < 4; q++){
      int r = (q & 1) ? r1 : r0;
      int c = 2*cl + ((q >> 1) ? 8 : 0);
      float sc = (r < 20 || r >= 30) ? 0.5f : 1.0f;
      float w0 = (r < 40 && c     < 10) ? sc * W_hh[r*10 + c    ] : 0.f;
      float w1 = (r < 40 && c + 1 < 10) ? sc * W_hh[r*10 + c + 1] : 0.f;
      uint32_t h2 = bf16pair(w0, w1);
      float h0 = __uint_as_float(h2 << 16);
      float h1 = __uint_as_float(h2 & 0xffff0000u);
      Hhi[mi][q] = h2;
      Hlo[mi][q] = bf16pair(w0 - h0, w1 - h1);
    }
  }

  float cA[5], cB[5], hA[10], hB[10];
  #pragma unroll
  for (int k = 0; k < 5;  k++){ cA[k]=0.f; cB[k]=0.f; }
  #pragma unroll
  for (int k = 0; k < 10; k++){ hA[k]=0.f; hB[k]=0.f; }

  float C[3][4][4];

  // ---- prologue: convert x_0, stage x_1, C = bias + W_ih@x_0 ----
  asm volatile("cp.async.wait_group 0;");
  __syncwarp();
  CONVERT_X();
  __syncwarp();            // conversions visible; s_x free
  STAGE_X(1);
  C_INIT();
  X_PASSES();

  #pragma unroll 1
  for (int t = 0; t < TSTEPS; t++){
    // ---- serial part: C += W_hh @ h_t (h pass, 3-pass hi/lo, K=16) ----
    #pragma unroll
    for (int ni = 0; ni < 4; ni++){
      int n = 8*ni + gr;
      uint32_t bh0 = s_hhi[n*HROW_W + cl];
      uint32_t bh1 = s_hhi[n*HROW_W + cl + 4];
      #pragma unroll
      for (int mi = 0; mi < 3; mi++){
        MMA_BF16(C[mi][ni], Hhi[mi], bh0, bh1);   // Uhi * hhi
        MMA_BF16(C[mi][ni], Hlo[mi], bh0, bh1);   // Ulo * hhi
      }
      uint32_t bl0 = s_hlo[n*HROW_W + cl];
      uint32_t bl1 = s_hlo[n*HROW_W + cl + 4];
      #pragma unroll
      for (int mi = 0; mi < 3; mi++)
        MMA_BF16(C[mi][ni], Hhi[mi], bl0, bl1);   // Uhi * hlo
    }
    // ---- store gates -> s_g ----
    #pragma unroll
    for (int mi = 0; mi < 3; mi++)
      #pragma unroll
      for (int ni = 0; ni < 4; ni++){
        int row0 = 16*mi + gr;
        int col  = 8*ni + 2*cl;
        *(float2*)&s_g[row0*GPAD + col] = make_float2(C[mi][ni][0], C[mi][ni][1]);
        if (mi < 2)
          *(float2*)&s_g[(row0+8)*GPAD + col] = make_float2(C[mi][ni][2], C[mi][ni][3]);
      }
    const bool more = (t + 1 < TSTEPS);
    if (more){
      asm volatile("cp.async.wait_group 0;");     // x_{t+1} staged
    }
    __syncwarp();   // gate stores visible; x_{t+1} staged for all lanes
    if (more){
      CONVERT_X();                                 // x_{t+1} -> bf16 hi/lo
    }
    __syncwarp();   // conversions visible; s_x free for restage
    if (t + 2 < TSTEPS){
      STAGE_X(t + 2);
    }

    // ---- overlapped region: next step's x-GEMM + this step's recurrence ----
    if (more){
      C_INIT();
      X_PASSES();          // C = bias + W_ih@x_{t+1}   (independent of h)
    }
    // recurrence for step t (reads s_g)
    float hnA[5], hnB[5];
    #pragma unroll
    for (int kk = 0; kk < 5; kk++){
      const int ri = 2*kk + half;
      float2 vi = *(const float2*)&s_g[(ri     )*GPAD + e0];
      float2 vf = *(const float2*)&s_g[(ri + 10)*GPAD + e0];
      float2 vg = *(const float2*)&s_g[(ri + 20)*GPAD + e0];
      float2 vo = *(const float2*)&s_g[(ri + 30)*GPAD + e0];
      float i0 = sig_from_half(vi.x), i1 = sig_from_half(vi.y);
      float f0 = sig_from_half(vf.x), f1 = sig_from_half(vf.y);
      float g0 = tanh_fast(vg.x),     g1 = tanh_fast(vg.y);
      float o0 = sig_from_half(vo.x), o1 = sig_from_half(vo.y);
      float cn0 = fmaf(f0, cA[kk], i0*g0);
      float cn1 = fmaf(f1, cB[kk], i1*g1);
      float hv0 = o0 * tanh_fast(cn0);
      float hv1 = o1 * tanh_fast(cn1);
      cA[kk]  = fmaxf(cn0, 0.f);       // ReLU on carried cell state
      cB[kk]  = fmaxf(cn1, 0.f);
      hnA[kk] = fmaxf(hv0, 0.f);       // ReLU on carried hidden
      hnB[kk] = fmaxf(hv1, 0.f);
    }
    #pragma unroll
    for (int kk = 0; kk < 5; kk++){
      float oA = __shfl_xor_sync(0xFFFFFFFFu, hnA[kk], 1);
      float oB = __shfl_xor_sync(0xFFFFFFFFu, hnB[kk], 1);
      hA[2*kk + half]     = hnA[kk];  hA[2*kk + 1 - half] = oA;
      hB[2*kk + half]     = hnB[kk];  hB[2*kk + 1 - half] = oB;
    }
    // ---- pack h_{t+1} (own element = lane) into bf16 hi/lo rows ----
    if (more){
      const float* hw = half ? hB : hA;
      const uint32_t hb = (uint32_t)(lane * HROW_W);
      #pragma unroll
      for (int m = 0; m < 5; m++){
        float a = hw[2*m], b = hw[2*m + 1];
        uint32_t h2 = bf16pair(a, b);
        float a_hi = __uint_as_float(h2 << 16);
        float b_hi = __uint_as_float(h2 & 0xffff0000u);
        s_hhi[hb + m] = h2;
        s_hlo[hb + m] = bf16pair(a - a_hi, b - b_hi);
      }
    }
    __syncwarp();   // packs visible for next iteration's h-MMA
  }

  // ---- head: FC(10->5) -> ReLU -> Linear(5->1) -> sigmoid (params via LDG) ----
  if (half == 0){
    float z0 = b_out[0], z1 = z0;
    #pragma unroll
    for (int u = 0; u < 5; u++){
      float y0 = b_fc[u], y1 = y0;
      #pragma unroll
      for (int k = 0; k < 10; k++){
        float w = W_fc[u*10 + k];
        y0 = fmaf(w, hA[k], y0);
        y1 = fmaf(w, hB[k], y1);
      }
      float wo = W_out[u];
      z0 = fmaf(wo, fmaxf(y0, 0.f), z0);
      z1 = fmaf(wo, fmaxf(y1, 0.f), z1);
    }
    const int b0 = blockElem + e0;
    if (b0 + 1 < Bn){
      float2 v;
      v.x = fmaf(0.5f, tanh_fast(0.5f * z0), 0.5f);
      v.y = fmaf(0.5f, tanh_fast(0.5f * z1), 0.5f);
      *(float2*)(out + b0) = v;
    } else if (b0 < Bn){
      out[b0] = fmaf(0.5f, tanh_fast(0.5f * z0), 0.5f);
    }
  }
}

extern "C" void kernel_launch(void* const* d_in, const int* in_sizes, int n_in,
                              void* d_out, int out_size) {
  const float* word  = (const float*)d_in[0];
  const float* W_ih  = (const float*)d_in[1];
  const float* W_hh  = (const float*)d_in[2];
  const float* b_ih  = (const float*)d_in[3];
  const float* b_hh  = (const float*)d_in[4];
  const float* W_fc  = (const float*)d_in[5];
  const float* b_fc  = (const float*)d_in[6];
  const float* W_out = (const float*)d_in[7];
  const float* b_out = (const float*)d_in[8];
  float* out = (float*)d_out;

  const int Bn = in_sizes[0] / (TSTEPS * INF);   // 65536
  const int blocks = (Bn + 31) / 32;             // 2048 single-warp blocks

  lstm_mma_kernel<<<blocks, 32>>>(word, W_ih, W_hh, b_ih, b_hh,
                                  W_fc, b_fc, W_out, b_out, out, Bn);
}

// round 17
// speedup vs baseline: 1.1074x; 1.0093x over previous
#include <cuda_runtime.h>
#include <cstdint>
#include <cstddef>

#define TSTEPS 32
#define INF    27
#define XROW_W 17   // u32 words per bf16 x row (k 0..31 used by mma, pads 0)
#define GPAD   36   // s_g row stride in floats (2-phase STS.64, conflict-free LDS.64)

__device__ __forceinline__ void cp8(uint32_t saddr, const void* gptr){
  asm volatile("cp.async.ca.shared.global [%0], [%1], 8;" :: "r"(saddr), "l"(gptr));
}
__device__ __forceinline__ float tanh_fast(float x){
  float r; asm("tanh.approx.f32 %0, %1;" : "=f"(r) : "f"(x)); return r;
}
__device__ __forceinline__ float sig_from_half(float a){   // acc holds x/2
  return fmaf(0.5f, tanh_fast(a), 0.5f);
}
__device__ __forceinline__ uint32_t bf16pair(float lo_val, float hi_val){
  uint32_t r; asm("cvt.rn.bf16x2.f32 %0, %1, %2;" : "=r"(r) : "f"(hi_val), "f"(lo_val));
  return r;
}
#define MMA_BF16(C, A, B0, B1) \
  asm volatile("mma.sync.aligned.m16n8k16.row.col.f32.bf16.bf16.f32 " \
    "{%0,%1,%2,%3}, {%4,%5,%6,%7}, {%8,%9}, {%0,%1,%2,%3};" \
    : "+f"((C)[0]), "+f"((C)[1]), "+f"((C)[2]), "+f"((C)[3]) \
    : "r"((A)[0]), "r"((A)[1]), "r"((A)[2]), "r"((A)[3]), \
      "r"(B0), "r"(B1))

// Single-warp blocks, 32 elems each, 14 blocks/SM. Per step:
// (1) convert x fp32 -> bf16 hi/lo in smem, (2) gates = W_ih@x + b via 3-pass
// bf16-split mma (W fragments register-resident), (3) gates through smem to
// the scalar recurrence (split-k lane pairs, MUFU.TANH activations).
// R17 deltas vs R14 (all LDS/STS-count only, numerics identical):
//   W_hh float2 pairs, gate float2 reads, GPAD 36.
__global__ void __launch_bounds__(32, 14) lstm_mma_kernel(
    const float* __restrict__ word,
    const float* __restrict__ W_ih, const float* __restrict__ W_hh,
    const float* __restrict__ b_ih, const float* __restrict__ b_hh,
    const float* __restrict__ W_fc, const float* __restrict__ b_fc,
    const float* __restrict__ W_out, const float* __restrict__ b_out,
    float* __restrict__ out, int Bn)
{
  __shared__ __align__(8) float2  s_whh2[40*6];      // row r: 5 j-pairs + pad
  __shared__ float s_wfc[50], s_bfc[5], s_wout[5], s_bout[1];
  __shared__ __align__(16) float   s_x[32*INF];      // fp32 x, SINGLE buffer
  __shared__ __align__(8) uint32_t s_xhi[32*XROW_W];
  __shared__ __align__(8) uint32_t s_xlo[32*XROW_W];
  __shared__ __align__(8) float    s_g[40*GPAD];     // gate preactivations

  const int lane = threadIdx.x;
  const int gr = lane >> 2, cl = lane & 3;     // mma fragment coords
  const int half = lane & 1, p = lane >> 1;    // recurrence pairing
  const int e0 = 2*p;
  const int blockElem = blockIdx.x * 32;
  const uint32_t sx0 = (uint32_t)__cvta_generic_to_shared(&s_x[0]);

  // stage t=0 x early (432 float2 over 32 lanes)
  {
    const float2* src = (const float2*)(word + ((size_t)blockElem) * INF);
    #pragma unroll
    for (int m = 0; m < 14; m++){
      int i2 = m*32 + lane;
      if (i2 < 432) cp8(sx0 + (uint32_t)(i2*8), src + i2);
    }
    asm volatile("cp.async.commit_group;");
  }

  // ---- shared fills ----
  // W_hh rows as float2 j-pairs, i/f/o rows pre-halved; pad pair = 0
  for (int idx = lane; idx < 40*6; idx += 32){
    int r = idx / 6, m = idx - r*6;
    float sc = (r < 20 || r >= 30) ? 0.5f : 1.0f;
    float w0 = (2*m     < 10) ? sc * W_hh[r*10 + 2*m    ] : 0.f;
    float w1 = (2*m + 1 < 10) ? sc * W_hh[r*10 + 2*m + 1] : 0.f;
    s_whh2[idx] = make_float2(w0, w1);
  }
  for (int idx = lane; idx < 50; idx += 32) s_wfc[idx] = W_fc[idx];
  if (lane < 5) { s_bfc[lane] = b_fc[lane]; s_wout[lane] = W_out[lane]; }
  if (lane == 0) s_bout[0] = b_out[0];
  s_xhi[lane*XROW_W + 14] = 0u; s_xhi[lane*XROW_W + 15] = 0u; s_xhi[lane*XROW_W + 16] = 0u;
  s_xlo[lane*XROW_W + 14] = 0u; s_xlo[lane*XROW_W + 15] = 0u; s_xlo[lane*XROW_W + 16] = 0u;

  // ---- W_ih fragments (hi/lo bf16 split), i/f/o rows pre-halved (verified) ----
  uint32_t Ahi[3][2][4], Alo[3][2][4];
  float cb0[3], cb1[3];
  #pragma unroll
  for (int mi = 0; mi < 3; mi++){
    int r0 = 16*mi + gr, r1 = r0 + 8;
    float s0 = (r0 < 20 || r0 >= 30) ? 0.5f : 1.0f;
    float s1 = (r1 < 20 || r1 >= 30) ? 0.5f : 1.0f;
    cb0[mi] = (r0 < 40) ? s0 * (b_ih[r0] + b_hh[r0]) : 0.f;
    cb1[mi] = (r1 < 40) ? s1 * (b_ih[r1] + b_hh[r1]) : 0.f;
    #pragma unroll
    for (int ki = 0; ki < 2; ki++){
      #pragma unroll
      for (int q = 0; q < 4; q++){
        int r = (q & 1) ? r1 : r0;
        int c = 16*ki + 2*cl + ((q >> 1) ? 8 : 0);
        float sc = (r < 20 || r >= 30) ? 0.5f : 1.0f;
        float w0 = (r < 40 && c     < 27) ? sc * W_ih[r*27 + c    ] : 0.f;
        float w1 = (r < 40 && c + 1 < 27) ? sc * W_ih[r*27 + c + 1] : 0.f;
        uint32_t h2 = bf16pair(w0, w1);
        float h0 = __uint_as_float(h2 << 16);
        float h1 = __uint_as_float(h2 & 0xffff0000u);
        Ahi[mi][ki][q] = h2;
        Alo[mi][ki][q] = bf16pair(w0 - h0, w1 - h1);
      }
    }
  }
  __syncwarp();

  float hA[10], hB[10], cA[5], cB[5];
  #pragma unroll
  for (int k = 0; k < 10; k++){ hA[k]=0.f; hB[k]=0.f; }
  #pragma unroll
  for (int k = 0; k < 5;  k++){ cA[k]=0.f; cB[k]=0.f; }

  const float2* whh2_b = s_whh2 + 6*half;   // own k rows: (2kk+half), stride 6

  #pragma unroll 1
  for (int t = 0; t < TSTEPS; t++){
    // x_t staged (prologue / previous iteration). Single group in flight.
    asm volatile("cp.async.wait_group 0;");
    __syncwarp();   // all lanes' cp done; also: prior step's xhi reads done

    // ---- convert own elem row fp32 -> bf16 hi/lo ----
    {
      const float* xr = &s_x[lane * INF];
      const uint32_t hb = (uint32_t)(lane * XROW_W);
      #pragma unroll
      for (int m = 0; m < 14; m++){
        float x0 = xr[2*m];
        float x1 = (2*m + 1 < INF) ? xr[2*m + 1] : 0.f;
        uint32_t h2 = bf16pair(x0, x1);
        float h0 = __uint_as_float(h2 << 16);
        float h1 = __uint_as_float(h2 & 0xffff0000u);
        s_xhi[hb + m] = h2;
        s_xlo[hb + m] = bf16pair(x0 - h0, x1 - h1);
      }
    }
    __syncwarp();   // conversions visible; s_x free for restage

    // ---- stage x_{t+1} into the (now free) single buffer ----
    if (t + 1 < TSTEPS){
      const float2* src = (const float2*)(word + ((size_t)(t+1)*Bn + blockElem) * INF);
      #pragma unroll
      for (int m = 0; m < 14; m++){
        int i2 = m*32 + lane;
        if (i2 < 432) cp8(sx0 + (uint32_t)(i2*8), src + i2);
      }
      asm volatile("cp.async.commit_group;");
    }

    // ---- gates = W_ih @ x + bias via 3-pass bf16-split mma ----
    float C[3][4][4];
    #pragma unroll
    for (int mi = 0; mi < 3; mi++)
      #pragma unroll
      for (int ni = 0; ni < 4; ni++){
        C[mi][ni][0] = cb0[mi]; C[mi][ni][1] = cb0[mi];
        C[mi][ni][2] = cb1[mi]; C[mi][ni][3] = cb1[mi];
      }
    #pragma unroll
    for (int ki = 0; ki < 2; ki++){
      #pragma unroll
      for (int ni = 0; ni < 4; ni++){
        int n = 8*ni + gr;
        uint32_t bh0 = s_xhi[n*XROW_W + 8*ki + cl];
        uint32_t bh1 = s_xhi[n*XROW_W + 8*ki + cl + 4];
        #pragma unroll
        for (int mi = 0; mi < 3; mi++){
          MMA_BF16(C[mi][ni], Ahi[mi][ki], bh0, bh1);   // Whi * xhi
          MMA_BF16(C[mi][ni], Alo[mi][ki], bh0, bh1);   // Wlo * xhi
        }
        uint32_t bl0 = s_xlo[n*XROW_W + 8*ki + cl];
        uint32_t bl1 = s_xlo[n*XROW_W + 8*ki + cl + 4];
        #pragma unroll
        for (int mi = 0; mi < 3; mi++)
          MMA_BF16(C[mi][ni], Ahi[mi][ki], bl0, bl1);   // Whi * xlo
      }
    }
    // ---- store gates: C frag (gr,2cl | +8) -> s_g[row][elem] ----
    #pragma unroll
    for (int mi = 0; mi < 3; mi++)
      #pragma unroll
      for (int ni = 0; ni < 4; ni++){
        int row0 = 16*mi + gr;
        int col  = 8*ni + 2*cl;
        *(float2*)&s_g[row0*GPAD + col] = make_float2(C[mi][ni][0], C[mi][ni][1]);
        if (mi < 2)
          *(float2*)&s_g[(row0+8)*GPAD + col] = make_float2(C[mi][ni][2], C[mi][ni][3]);
      }
    __syncwarp();

    // ---- scalar recurrence; own k = 2kk + half (interleaved split-k) ----
    float hnA[5], hnB[5];
    #pragma unroll
    for (int kk = 0; kk < 5; kk++){
      const int ri = 2*kk + half;
      float2 vi = *(const float2*)&s_g[(ri     )*GPAD + e0];
      float2 vf = *(const float2*)&s_g[(ri + 10)*GPAD + e0];
      float2 vg = *(const float2*)&s_g[(ri + 20)*GPAD + e0];
      float2 vo = *(const float2*)&s_g[(ri + 30)*GPAD + e0];
      float ai0 = vi.x, ai1 = vi.y;
      float af0 = vf.x, af1 = vf.y;
      float ag0 = vg.x, ag1 = vg.y;
      float ao0 = vo.x, ao1 = vo.y;
      #pragma unroll
      for (int m = 0; m < 5; m++){
        float2 ui = whh2_b[12*kk       + m];
        float2 uf = whh2_b[12*kk +  60 + m];
        float2 ug = whh2_b[12*kk + 120 + m];
        float2 uo = whh2_b[12*kk + 180 + m];
        float ha0 = hA[2*m], ha1 = hA[2*m+1];
        float hb0 = hB[2*m], hb1 = hB[2*m+1];
        ai0 = fmaf(ui.x, ha0, ai0);  ai0 = fmaf(ui.y, ha1, ai0);
        ai1 = fmaf(ui.x, hb0, ai1);  ai1 = fmaf(ui.y, hb1, ai1);
        af0 = fmaf(uf.x, ha0, af0);  af0 = fmaf(uf.y, ha1, af0);
        af1 = fmaf(uf.x, hb0, af1);  af1 = fmaf(uf.y, hb1, af1);
        ag0 = fmaf(ug.x, ha0, ag0);  ag0 = fmaf(ug.y, ha1, ag0);
        ag1 = fmaf(ug.x, hb0, ag1);  ag1 = fmaf(ug.y, hb1, ag1);
        ao0 = fmaf(uo.x, ha0, ao0);  ao0 = fmaf(uo.y, ha1, ao0);
        ao1 = fmaf(uo.x, hb0, ao1);  ao1 = fmaf(uo.y, hb1, ao1);
      }
      float i0 = sig_from_half(ai0), i1 = sig_from_half(ai1);
      float f0 = sig_from_half(af0), f1 = sig_from_half(af1);
      float g0 = tanh_fast(ag0),     g1 = tanh_fast(ag1);
      float o0 = sig_from_half(ao0), o1 = sig_from_half(ao1);
      float cn0 = fmaf(f0, cA[kk], i0*g0);
      float cn1 = fmaf(f1, cB[kk], i1*g1);
      float hv0 = o0 * tanh_fast(cn0);
      float hv1 = o1 * tanh_fast(cn1);
      cA[kk]  = fmaxf(cn0, 0.f);       // ReLU on carried cell state
      cB[kk]  = fmaxf(cn1, 0.f);
      hnA[kk] = fmaxf(hv0, 0.f);       // ReLU on carried hidden
      hnB[kk] = fmaxf(hv1, 0.f);
    }
    #pragma unroll
    for (int kk = 0; kk < 5; kk++){
      float oA = __shfl_xor_sync(0xFFFFFFFFu, hnA[kk], 1);
      float oB = __shfl_xor_sync(0xFFFFFFFFu, hnB[kk], 1);
      hA[2*kk + half]     = hnA[kk];  hA[2*kk + 1 - half] = oA;
      hB[2*kk + half]     = hnB[kk];  hB[2*kk + 1 - half] = oB;
    }
    // s_g overwrite next step is ordered by the two syncwarps at next
    // iteration's top (wait + post-convert) — warp-local memory ordering.
  }

  // ---- head: FC(10->5) -> ReLU -> Linear(5->1) -> sigmoid ----
  if (half == 0){
    float z0 = s_bout[0], z1 = s_bout[0];
    #pragma unroll
    for (int u = 0; u < 5; u++){
      float y0 = s_bfc[u], y1 = s_bfc[u];
      #pragma unroll
      for (int k = 0; k < 10; k++){
        float w = s_wfc[u*10 + k];
        y0 = fmaf(w, hA[k], y0);
        y1 = fmaf(w, hB[k], y1);
      }
      z0 = fmaf(s_wout[u], fmaxf(y0, 0.f), z0);
      z1 = fmaf(s_wout[u], fmaxf(y1, 0.f), z1);
    }
    const int b0 = blockElem + e0;
    if (b0 + 1 < Bn){
      float2 v;
      v.x = fmaf(0.5f, tanh_fast(0.5f * z0), 0.5f);
      v.y = fmaf(0.5f, tanh_fast(0.5f * z1), 0.5f);
      *(float2*)(out + b0) = v;
    } else if (b0 < Bn){
      out[b0] = fmaf(0.5f, tanh_fast(0.5f * z0), 0.5f);
    }
  }
}

extern "C" void kernel_launch(void* const* d_in, const int* in_sizes, int n_in,
                              void* d_out, int out_size) {
  const float* word  = (const float*)d_in[0];
  const float* W_ih  = (const float*)d_in[1];
  const float* W_hh  = (const float*)d_in[2];
  const float* b_ih  = (const float*)d_in[3];
  const float* b_hh  = (const float*)d_in[4];
  const float* W_fc  = (const float*)d_in[5];
  const float* b_fc  = (const float*)d_in[6];
  const float* W_out = (const float*)d_in[7];
  const float* b_out = (const float*)d_in[8];
  float* out = (float*)d_out;

  const int Bn = in_sizes[0] / (TSTEPS * INF);   // 65536
  const int blocks = (Bn + 31) / 32;             // 2048 single-warp blocks

  lstm_mma_kernel<<<blocks, 32>>>(word, W_ih, W_hh, b_ih, b_hh,
                                  W_fc, b_fc, W_out, b_out, out, Bn);
}